// round 10
// baseline (speedup 1.0000x reference)
#include <cuda_runtime.h>
#include <cuda_bf16.h>
#include <cstdint>

#define NTOK 8192
#define INDIM 256
#define HID 128
#define BN 64
#define NT 64          // m-tiles per half (4096/64)

// ---------------- device scratch (no allocs allowed) ----------------
__device__ __nv_bfloat16 g_Zhi[NTOK * HID];
__device__ __nv_bfloat16 g_Zlo[NTOK * HID];
__device__ float g_outpart[2 * NTOK * HID];
__device__ float g_rs[2 * NTOK];
__device__ float g_inv[NTOK];

// ---------------- helpers ----------------
__device__ __forceinline__ uint32_t smem_u32(const void* p) {
    uint32_t a;
    asm("{ .reg .u64 t; cvta.to.shared.u64 t, %1; cvt.u32.u64 %0, t; }" : "=r"(a) : "l"(p));
    return a;
}
__device__ __forceinline__ void ldsm_x4(uint32_t a[4], uint32_t addr) {
    asm volatile("ldmatrix.sync.aligned.m8n8.x4.shared.b16 {%0,%1,%2,%3}, [%4];"
                 : "=r"(a[0]), "=r"(a[1]), "=r"(a[2]), "=r"(a[3]) : "r"(addr));
}
__device__ __forceinline__ void ldsm_x4t(uint32_t a[4], uint32_t addr) {
    asm volatile("ldmatrix.sync.aligned.m8n8.x4.trans.shared.b16 {%0,%1,%2,%3}, [%4];"
                 : "=r"(a[0]), "=r"(a[1]), "=r"(a[2]), "=r"(a[3]) : "r"(addr));
}
__device__ __forceinline__ void mma16816(float c[4], const uint32_t a[4], const uint32_t* b) {
    asm volatile("mma.sync.aligned.m16n8k16.row.col.f32.bf16.bf16.f32 "
                 "{%0,%1,%2,%3}, {%4,%5,%6,%7}, {%8,%9}, {%0,%1,%2,%3};"
                 : "+f"(c[0]), "+f"(c[1]), "+f"(c[2]), "+f"(c[3])
                 : "r"(a[0]), "r"(a[1]), "r"(a[2]), "r"(a[3]), "r"(b[0]), "r"(b[1]));
}
// pack two f32 -> bf16x2: %1 -> upper half, %2 -> lower half
__device__ __forceinline__ uint32_t pack_bf16x2(float hi_upper, float lo_lower) {
    uint32_t r;
    asm("cvt.rn.bf16x2.f32 %0, %1, %2;" : "=r"(r) : "f"(hi_upper), "f"(lo_lower));
    return r;
}
__device__ __forceinline__ void cpasync16(uint32_t saddr, const void* gptr) {
    asm volatile("cp.async.cg.shared.global [%0], [%1], 16;" :: "r"(saddr), "l"(gptr));
}
#define CP_COMMIT() asm volatile("cp.async.commit_group;" ::: "memory")
#define CP_WAIT0()  asm volatile("cp.async.wait_group 0;" ::: "memory")

// ---------------- k2 smem layout (bf16, row stride 136 elems = 272 B) ----------------
#define ZR_HI   0u          // [128][136]  34816 B
#define ZR_LO   34816u
#define ZM_BUF0 69632u      // each buf: HI at +0, LO at +17408 (34816 B total)
#define ZM_BUF1 104448u
#define ZM_LO_D 17408u
#define SM_K2_BYTES 139264u
#define RSTR 272u           // row stride bytes

// ===========================================================================
// K1: Z = X W^T (fp32 FFMA), emit bf16 hi/lo (row-major only)
// ===========================================================================
__global__ __launch_bounds__(256) void k1_gemm_z(const float* __restrict__ X,
                                                 const float* __restrict__ W)
{
    __shared__ float Wt[64][129];
    __shared__ float Xs[32][68];

    const int t    = threadIdx.x;
    const int row0 = blockIdx.x * 32;
    const int w    = t >> 5;
    const int lane = t & 31;

    float acc[4][4];
#pragma unroll
    for (int i = 0; i < 4; i++)
#pragma unroll
        for (int q = 0; q < 4; q++) acc[i][q] = 0.f;

    for (int c = 0; c < 4; c++) {
        const int i0 = c * 64;
#pragma unroll
        for (int rep = 0; rep < 8; rep++) {
            int f = rep * 256 + t;
            int h = f >> 4;
            int ii = (f & 15) << 2;
            float4 v = *(const float4*)&W[h * INDIM + i0 + ii];
            Wt[ii + 0][h] = v.x; Wt[ii + 1][h] = v.y;
            Wt[ii + 2][h] = v.z; Wt[ii + 3][h] = v.w;
        }
#pragma unroll
        for (int rep = 0; rep < 2; rep++) {
            int f = rep * 256 + t;
            int r = f >> 4;
            int ii = (f & 15) << 2;
            *(float4*)&Xs[r][ii] = *(const float4*)&X[(row0 + r) * INDIM + i0 + ii];
        }
        __syncthreads();
#pragma unroll 8
        for (int ii = 0; ii < 64; ii++) {
            float xv[4], wv[4];
#pragma unroll
            for (int i = 0; i < 4; i++) xv[i] = Xs[4 * w + i][ii];
#pragma unroll
            for (int q = 0; q < 4; q++) wv[q] = Wt[ii][lane + 32 * q];
#pragma unroll
            for (int i = 0; i < 4; i++)
#pragma unroll
                for (int q = 0; q < 4; q++)
                    acc[i][q] = fmaf(xv[i], wv[q], acc[i][q]);
        }
        __syncthreads();
    }

#pragma unroll
    for (int i = 0; i < 4; i++)
#pragma unroll
        for (int q = 0; q < 4; q++) {
            int n = row0 + 4 * w + i;
            int h = lane + 32 * q;
            float z = acc[i][q];
            __nv_bfloat16 hb = __float2bfloat16(z);
            float hf = __bfloat162float(hb);
            __nv_bfloat16 lb = __float2bfloat16(z - hf);
            g_Zhi[n * HID + h] = hb;
            g_Zlo[n * HID + h] = lb;
        }
}

// ===========================================================================
// K2: fused mma.sync pipeline with cp.async double-buffered Zm.
// 128 CTAs = 64 rowblocks x 2 halves, 256 threads.
// ===========================================================================
__device__ __forceinline__ void issue_zm(char* smem, uint32_t sb, uint32_t buf,
                                         int m0, int tid)
{
    // 2 arrays (hi, lo) x 64 rows x 16 chunks of 16B = 2048 cp.async; 8/thread
#pragma unroll
    for (int it = 0; it < 8; it++) {
        int f   = it * 256 + tid;
        int arr = f >> 10;            // 0 = hi, 1 = lo
        int rest = f & 1023;
        int r  = rest >> 4;
        int ch = rest & 15;
        uint32_t dst = sb + buf + (uint32_t)arr * ZM_LO_D + (uint32_t)r * RSTR + (uint32_t)ch * 16u;
        const __nv_bfloat16* src = (arr ? g_Zlo : g_Zhi) + (size_t)(m0 + r) * HID + ch * 8;
        cpasync16(dst, src);
    }
}

__global__ __launch_bounds__(256) void k2_fused(float* __restrict__ A)
{
    extern __shared__ __align__(16) char smem[];
    const uint32_t sb = smem_u32(smem);

    const int tid  = threadIdx.x;
    const int w    = tid >> 5;
    const int lane = tid & 31;
    const int qr   = lane >> 2;   // 0..7
    const int qc   = lane & 3;    // quad column
    const int rb   = blockIdx.x >> 1;
    const int half = blockIdx.x & 1;
    const int row0 = rb * 128;
    const int mbase = half * (NTOK / 2);

    // ---- load Zr hi/lo (one-time, regular stores) ----
#pragma unroll
    for (int it = 0; it < 8; it++) {
        int f = it * 256 + tid;
        int r = f >> 4, ch = f & 15;
        uint32_t off = (uint32_t)r * RSTR + (uint32_t)ch * 16u;
        *(uint4*)(smem + ZR_HI + off) = *(const uint4*)&g_Zhi[(size_t)(row0 + r) * HID + ch * 8];
        *(uint4*)(smem + ZR_LO + off) = *(const uint4*)&g_Zlo[(size_t)(row0 + r) * HID + ch * 8];
    }

    // per-thread ldmatrix offsets
    const uint32_t aAddr  = sb + ZR_HI + (uint32_t)(16 * w + (lane & 15)) * RSTR
                            + (uint32_t)((lane >> 4) & 1) * 16u;                    // A (Zr), x4
    const uint32_t b1off4 = (uint32_t)(lane & 7) * RSTR + (uint32_t)((lane >> 3) & 1) * 16u
                            + (uint32_t)((lane >> 4) & 1) * (8u * RSTR);            // MMA1 B, x4 (n=16)
    const uint32_t b2off4 = (uint32_t)((lane & 7) + 8 * ((lane >> 3) & 1)) * RSTR
                            + (uint32_t)((lane >> 4) & 1) * 16u;                    // MMA2 B, x4t (n=16)

    float o[16][4];
#pragma unroll
    for (int nn = 0; nn < 16; nn++)
#pragma unroll
        for (int i = 0; i < 4; i++) o[nn][i] = 0.f;
    float rs0 = 0.f, rs1 = 0.f;

    // ---- prologue: stream tile 0 ----
    issue_zm(smem, sb, ZM_BUF0, mbase, tid);
    CP_COMMIT();

    for (int t = 0; t < NT; t++) {
        const int m0 = mbase + t * BN;
        const uint32_t zmB = sb + ((t & 1) ? ZM_BUF1 : ZM_BUF0);

        CP_WAIT0();          // tile t's group complete (this thread)
        __syncthreads();     // all threads' data visible; prev compute done (WAR-safe)

        if (t + 1 < NT) {    // stream tile t+1, overlapping compute below
            issue_zm(smem, sb, ((t + 1) & 1) ? ZM_BUF1 : ZM_BUF0, m0 + BN, tid);
            CP_COMMIT();
        }

        // ---- MMA1: S = ZrHi ZmHi^T + ZrHi ZmLo^T + ZrLo ZmHi^T ----
        float c[8][4];
#pragma unroll
        for (int nn = 0; nn < 8; nn++)
#pragma unroll
            for (int i = 0; i < 4; i++) c[nn][i] = 0.f;

#pragma unroll
        for (int kk = 0; kk < 8; kk++) {
            uint32_t ah[4], al[4];
            ldsm_x4(ah, aAddr + kk * 32u);
            ldsm_x4(al, aAddr + (ZR_LO - ZR_HI) + kk * 32u);
#pragma unroll
            for (int nn2 = 0; nn2 < 4; nn2++) {
                uint32_t bh[4], bl[4];
                uint32_t ba = zmB + (uint32_t)nn2 * (16u * RSTR) + kk * 32u + b1off4;
                ldsm_x4(bh, ba);
                ldsm_x4(bl, ba + ZM_LO_D);
                mma16816(c[2 * nn2],     ah, bh);
                mma16816(c[2 * nn2],     ah, bl);
                mma16816(c[2 * nn2],     al, bh);
                mma16816(c[2 * nn2 + 1], ah, bh + 2);
                mma16816(c[2 * nn2 + 1], ah, bl + 2);
                mma16816(c[2 * nn2 + 1], al, bh + 2);
            }
        }

        // ---- epilogue in registers: relu, rowsum, A store, pack S hi/lo ----
        uint32_t shi[8][2], slo[8][2];
#pragma unroll
        for (int nn = 0; nn < 8; nn++) {
#pragma unroll
            for (int i = 0; i < 4; i++) c[nn][i] = fmaxf(c[nn][i], 0.f);
            rs0 += c[nn][0] + c[nn][1];
            rs1 += c[nn][2] + c[nn][3];
            uint32_t h0 = pack_bf16x2(c[nn][1], c[nn][0]);
            uint32_t h1 = pack_bf16x2(c[nn][3], c[nn][2]);
            shi[nn][0] = h0; shi[nn][1] = h1;
            float l00 = c[nn][0] - __uint_as_float(h0 << 16);
            float l01 = c[nn][1] - __uint_as_float(h0 & 0xFFFF0000u);
            float l10 = c[nn][2] - __uint_as_float(h1 << 16);
            float l11 = c[nn][3] - __uint_as_float(h1 & 0xFFFF0000u);
            slo[nn][0] = pack_bf16x2(l01, l00);
            slo[nn][1] = pack_bf16x2(l11, l10);
            size_t col = (size_t)m0 + nn * 8 + 2 * qc;
            *(float2*)&A[(size_t)(row0 + 16 * w + qr) * NTOK + col]     = make_float2(c[nn][0], c[nn][1]);
            *(float2*)&A[(size_t)(row0 + 16 * w + qr + 8) * NTOK + col] = make_float2(c[nn][2], c[nn][3]);
        }

        // ---- MMA2: out += SHi Zm(hi) + SHi Zm(lo) + SLo Zm(hi) ----
#pragma unroll
        for (int kk = 0; kk < 4; kk++) {
            uint32_t ah[4] = { shi[2 * kk][0], shi[2 * kk][1], shi[2 * kk + 1][0], shi[2 * kk + 1][1] };
            uint32_t al[4] = { slo[2 * kk][0], slo[2 * kk][1], slo[2 * kk + 1][0], slo[2 * kk + 1][1] };
#pragma unroll
            for (int nn2 = 0; nn2 < 8; nn2++) {
                uint32_t bh[4], bl[4];
                uint32_t ba = zmB + (uint32_t)kk * (16u * RSTR) + (uint32_t)nn2 * 32u + b2off4;
                ldsm_x4t(bh, ba);
                ldsm_x4t(bl, ba + ZM_LO_D);
                mma16816(o[2 * nn2],     ah, bh);
                mma16816(o[2 * nn2],     ah, bl);
                mma16816(o[2 * nn2],     al, bh);
                mma16816(o[2 * nn2 + 1], ah, bh + 2);
                mma16816(o[2 * nn2 + 1], ah, bl + 2);
                mma16816(o[2 * nn2 + 1], al, bh + 2);
            }
        }
    }

    // ---- final: rowsum quad-reduce + store out partials ----
    rs0 += __shfl_xor_sync(0xffffffffu, rs0, 1);
    rs0 += __shfl_xor_sync(0xffffffffu, rs0, 2);
    rs1 += __shfl_xor_sync(0xffffffffu, rs1, 1);
    rs1 += __shfl_xor_sync(0xffffffffu, rs1, 2);
    if (qc == 0) {
        g_rs[(size_t)half * NTOK + row0 + 16 * w + qr]     = rs0;
        g_rs[(size_t)half * NTOK + row0 + 16 * w + qr + 8] = rs1;
    }
    float* dst = g_outpart + (size_t)half * NTOK * HID;
#pragma unroll
    for (int nn = 0; nn < 16; nn++) {
        size_t col = (size_t)nn * 8 + 2 * qc;
        *(float2*)&dst[(size_t)(row0 + 16 * w + qr) * HID + col]     = make_float2(o[nn][0], o[nn][1]);
        *(float2*)&dst[(size_t)(row0 + 16 * w + qr + 8) * HID + col] = make_float2(o[nn][2], o[nn][3]);
    }
}

// ===========================================================================
// K3a: inverse row sums
// ===========================================================================
__global__ __launch_bounds__(256) void k3_inv()
{
    int n = blockIdx.x * blockDim.x + threadIdx.x;
    g_inv[n] = 1.f / (g_rs[n] + g_rs[NTOK + n] + 1e-6f);
}

// K3b: out = (p0 + p1) * inv
__global__ __launch_bounds__(256) void k3_out(float* __restrict__ outp)
{
    int idx = blockIdx.x * blockDim.x + threadIdx.x;
    const float4* p0 = (const float4*)g_outpart;
    const float4* p1 = p0 + (NTOK * HID / 4);
    float4 a = p0[idx], b = p1[idx];
    float inv = g_inv[idx >> 5];
    float4 ov;
    ov.x = (a.x + b.x) * inv; ov.y = (a.y + b.y) * inv;
    ov.z = (a.z + b.z) * inv; ov.w = (a.w + b.w) * inv;
    ((float4*)outp)[idx] = ov;
}

// K3c: A *= inv[row]
__global__ __launch_bounds__(256) void k3_norm(float* __restrict__ A)
{
    long long i      = (long long)blockIdx.x * blockDim.x + threadIdx.x;
    long long stride = (long long)gridDim.x * blockDim.x;
    const long long total = (long long)NTOK * NTOK / 4;
    float4* A4 = (float4*)A;
    for (long long idx = i; idx < total; idx += stride) {
        int row  = (int)(idx >> 11);
        float sc = g_inv[row];
        float4 v = A4[idx];
        v.x *= sc; v.y *= sc; v.z *= sc; v.w *= sc;
        A4[idx] = v;
    }
}

extern "C" void kernel_launch(void* const* d_in, const int* in_sizes, int n_in,
                              void* d_out, int out_size)
{
    (void)in_sizes; (void)n_in; (void)out_size;
    const float* X = (const float*)d_in[0];
    const float* W = (const float*)d_in[1];
    float* outp = (float*)d_out;
    float* A    = (float*)d_out + (size_t)NTOK * HID;

    cudaFuncSetAttribute(k2_fused, cudaFuncAttributeMaxDynamicSharedMemorySize, SM_K2_BYTES);

    k1_gemm_z<<<NTOK / 32, 256>>>(X, W);
    k2_fused<<<128, 256, SM_K2_BYTES>>>(A);
    k3_inv<<<NTOK / 256, 256>>>();
    k3_out<<<(NTOK * HID / 4) / 256, 256>>>(outp);
    k3_norm<<<16384, 256>>>(A);
}

// round 13
// speedup vs baseline: 1.3215x; 1.3215x over previous
#include <cuda_runtime.h>
#include <cuda_bf16.h>
#include <cstdint>

#define NTOK 8192
#define INDIM 256
#define HID 128
#define BN 64
#define NT 64          // m-tiles per half (4096/64)

// ---------------- device scratch (no allocs allowed) ----------------
__device__ __nv_bfloat16 g_Zhi[NTOK * HID];
__device__ __nv_bfloat16 g_Zlo[NTOK * HID];
__device__ float g_outpart[2 * NTOK * HID];
__device__ float g_rs[2 * NTOK];
__device__ float g_inv[NTOK];

// ---------------- helpers ----------------
__device__ __forceinline__ uint32_t smem_u32(const void* p) {
    uint32_t a;
    asm("{ .reg .u64 t; cvta.to.shared.u64 t, %1; cvt.u32.u64 %0, t; }" : "=r"(a) : "l"(p));
    return a;
}
__device__ __forceinline__ void ldsm_x4(uint32_t a[4], uint32_t addr) {
    asm volatile("ldmatrix.sync.aligned.m8n8.x4.shared.b16 {%0,%1,%2,%3}, [%4];"
                 : "=r"(a[0]), "=r"(a[1]), "=r"(a[2]), "=r"(a[3]) : "r"(addr));
}
__device__ __forceinline__ void ldsm_x2(uint32_t b[2], uint32_t addr) {
    asm volatile("ldmatrix.sync.aligned.m8n8.x2.shared.b16 {%0,%1}, [%2];"
                 : "=r"(b[0]), "=r"(b[1]) : "r"(addr));
}
__device__ __forceinline__ void ldsm_x2t(uint32_t b[2], uint32_t addr) {
    asm volatile("ldmatrix.sync.aligned.m8n8.x2.trans.shared.b16 {%0,%1}, [%2];"
                 : "=r"(b[0]), "=r"(b[1]) : "r"(addr));
}
__device__ __forceinline__ void mma16816(float c[4], const uint32_t a[4], const uint32_t b[2]) {
    asm volatile("mma.sync.aligned.m16n8k16.row.col.f32.bf16.bf16.f32 "
                 "{%0,%1,%2,%3}, {%4,%5,%6,%7}, {%8,%9}, {%0,%1,%2,%3};"
                 : "+f"(c[0]), "+f"(c[1]), "+f"(c[2]), "+f"(c[3])
                 : "r"(a[0]), "r"(a[1]), "r"(a[2]), "r"(a[3]), "r"(b[0]), "r"(b[1]));
}
// pack two f32 -> bf16x2: %1 -> upper half, %2 -> lower half
__device__ __forceinline__ uint32_t pack_bf16x2(float hi_upper, float lo_lower) {
    uint32_t r;
    asm("cvt.rn.bf16x2.f32 %0, %1, %2;" : "=r"(r) : "f"(hi_upper), "f"(lo_lower));
    return r;
}
__device__ __forceinline__ void cpasync16(uint32_t saddr, const void* gptr) {
    asm volatile("cp.async.cg.shared.global [%0], [%1], 16;" :: "r"(saddr), "l"(gptr));
}
#define CP_COMMIT() asm volatile("cp.async.commit_group;" ::: "memory")
#define CP_WAIT0()  asm volatile("cp.async.wait_group 0;" ::: "memory")

// ---------------- k2 smem layout (bf16, row stride 136 elems = 272 B) ----------------
#define ZR_HI   0u          // [128][136]  34816 B
#define ZR_LO   34816u
#define ZM_BUF0 69632u      // each buf: HI at +0, LO at +17408 (34816 B total)
#define ZM_BUF1 104448u
#define ZM_LO_D 17408u
#define SM_K2_BYTES 139264u
#define RSTR 272u           // row stride bytes

// ===========================================================================
// K1: Z = X W^T (fp32 FFMA), emit bf16 hi/lo (row-major only)
// ===========================================================================
__global__ __launch_bounds__(256) void k1_gemm_z(const float* __restrict__ X,
                                                 const float* __restrict__ W)
{
    __shared__ float Wt[64][129];
    __shared__ float Xs[32][68];

    const int t    = threadIdx.x;
    const int row0 = blockIdx.x * 32;
    const int w    = t >> 5;
    const int lane = t & 31;

    float acc[4][4];
#pragma unroll
    for (int i = 0; i < 4; i++)
#pragma unroll
        for (int q = 0; q < 4; q++) acc[i][q] = 0.f;

    for (int c = 0; c < 4; c++) {
        const int i0 = c * 64;
#pragma unroll
        for (int rep = 0; rep < 8; rep++) {
            int f = rep * 256 + t;
            int h = f >> 4;
            int ii = (f & 15) << 2;
            float4 v = *(const float4*)&W[h * INDIM + i0 + ii];
            Wt[ii + 0][h] = v.x; Wt[ii + 1][h] = v.y;
            Wt[ii + 2][h] = v.z; Wt[ii + 3][h] = v.w;
        }
#pragma unroll
        for (int rep = 0; rep < 2; rep++) {
            int f = rep * 256 + t;
            int r = f >> 4;
            int ii = (f & 15) << 2;
            *(float4*)&Xs[r][ii] = *(const float4*)&X[(row0 + r) * INDIM + i0 + ii];
        }
        __syncthreads();
#pragma unroll 8
        for (int ii = 0; ii < 64; ii++) {
            float xv[4], wv[4];
#pragma unroll
            for (int i = 0; i < 4; i++) xv[i] = Xs[4 * w + i][ii];
#pragma unroll
            for (int q = 0; q < 4; q++) wv[q] = Wt[ii][lane + 32 * q];
#pragma unroll
            for (int i = 0; i < 4; i++)
#pragma unroll
                for (int q = 0; q < 4; q++)
                    acc[i][q] = fmaf(xv[i], wv[q], acc[i][q]);
        }
        __syncthreads();
    }

#pragma unroll
    for (int i = 0; i < 4; i++)
#pragma unroll
        for (int q = 0; q < 4; q++) {
            int n = row0 + 4 * w + i;
            int h = lane + 32 * q;
            float z = acc[i][q];
            __nv_bfloat16 hb = __float2bfloat16(z);
            float hf = __bfloat162float(hb);
            __nv_bfloat16 lb = __float2bfloat16(z - hf);
            g_Zhi[n * HID + h] = hb;
            g_Zlo[n * HID + h] = lb;
        }
}

// ===========================================================================
// K2: R9 structure (x2 ldmatrix, register-reuse S) + cp.async double-buffered
// Zm as the ONLY change. 128 CTAs = 64 rowblocks x 2 halves, 256 threads.
// ===========================================================================
__device__ __forceinline__ void issue_zm(uint32_t sb, uint32_t buf, int m0, int tid)
{
    // 2 arrays (hi, lo) x 64 rows x 16 chunks of 16B = 2048 cp.async; 8/thread
#pragma unroll
    for (int it = 0; it < 8; it++) {
        int f    = it * 256 + tid;
        int arr  = f >> 10;            // 0 = hi, 1 = lo
        int rest = f & 1023;
        int r  = rest >> 4;
        int ch = rest & 15;
        uint32_t dst = sb + buf + (uint32_t)arr * ZM_LO_D + (uint32_t)r * RSTR + (uint32_t)ch * 16u;
        const __nv_bfloat16* src = (arr ? g_Zlo : g_Zhi) + (size_t)(m0 + r) * HID + ch * 8;
        cpasync16(dst, src);
    }
}

__global__ __launch_bounds__(256) void k2_fused(float* __restrict__ A)
{
    extern __shared__ __align__(16) char smem[];
    const uint32_t sb = smem_u32(smem);

    const int tid  = threadIdx.x;
    const int w    = tid >> 5;
    const int lane = tid & 31;
    const int qr   = lane >> 2;   // 0..7
    const int qc   = lane & 3;    // quad column
    const int rb   = blockIdx.x >> 1;
    const int half = blockIdx.x & 1;
    const int row0 = rb * 128;
    const int mbase = half * (NTOK / 2);

    // ---- load Zr hi/lo (one-time) ----
#pragma unroll
    for (int it = 0; it < 8; it++) {
        int f = it * 256 + tid;
        int r = f >> 4, ch = f & 15;
        uint32_t off = (uint32_t)r * RSTR + (uint32_t)ch * 16u;
        *(uint4*)(smem + ZR_HI + off) = *(const uint4*)&g_Zhi[(size_t)(row0 + r) * HID + ch * 8];
        *(uint4*)(smem + ZR_LO + off) = *(const uint4*)&g_Zlo[(size_t)(row0 + r) * HID + ch * 8];
    }

    // per-thread ldmatrix offsets (identical to R9)
    const uint32_t aAddr  = sb + ZR_HI + (uint32_t)(16 * w + (lane & 15)) * RSTR
                            + (uint32_t)((lane >> 4) & 1) * 16u;              // A (Zr), x4 non-trans
    const uint32_t b1off  = (uint32_t)(lane & 7) * RSTR + (uint32_t)((lane >> 3) & 1) * 16u; // MMA1 B, x2
    const uint32_t b2off  = (uint32_t)((lane & 7) + 8 * ((lane >> 3) & 1)) * RSTR;           // MMA2 B, x2.trans

    float o[16][4];
#pragma unroll
    for (int nn = 0; nn < 16; nn++)
#pragma unroll
        for (int i = 0; i < 4; i++) o[nn][i] = 0.f;
    float rs0 = 0.f, rs1 = 0.f;

    // ---- prologue: stream tile 0 ----
    issue_zm(sb, ZM_BUF0, mbase, tid);
    CP_COMMIT();

    for (int t = 0; t < NT; t++) {
        const int m0 = mbase + t * BN;
        const uint32_t zmB = sb + ((t & 1) ? ZM_BUF1 : ZM_BUF0);

        CP_WAIT0();          // tile t's data arrived (this thread's issues)
        __syncthreads();     // all threads' data visible; prev compute done (WAR-safe)

        if (t + 1 < NT) {    // stream tile t+1 into the other buffer, overlapping compute
            issue_zm(sb, ((t + 1) & 1) ? ZM_BUF1 : ZM_BUF0, m0 + BN, tid);
            CP_COMMIT();
        }

        // ---- MMA1: S = ZrHi ZmHi^T + ZrHi ZmLo^T + ZrLo ZmHi^T ----
        float c[8][4];
#pragma unroll
        for (int nn = 0; nn < 8; nn++)
#pragma unroll
            for (int i = 0; i < 4; i++) c[nn][i] = 0.f;

#pragma unroll
        for (int kk = 0; kk < 8; kk++) {
            uint32_t ah[4], al[4];
            ldsm_x4(ah, aAddr + kk * 32u);
            ldsm_x4(al, aAddr + (ZR_LO - ZR_HI) + kk * 32u);
#pragma unroll
            for (int nn = 0; nn < 8; nn++) {
                uint32_t bh[2], bl[2];
                uint32_t ba = zmB + (uint32_t)nn * (8u * RSTR) + kk * 32u + b1off;
                ldsm_x2(bh, ba);
                ldsm_x2(bl, ba + ZM_LO_D);
                mma16816(c[nn], ah, bh);
                mma16816(c[nn], ah, bl);
                mma16816(c[nn], al, bh);
            }
        }

        // ---- epilogue in registers: relu, rowsum, A store, pack S hi/lo ----
        uint32_t shi[8][2], slo[8][2];
#pragma unroll
        for (int nn = 0; nn < 8; nn++) {
#pragma unroll
            for (int i = 0; i < 4; i++) c[nn][i] = fmaxf(c[nn][i], 0.f);
            rs0 += c[nn][0] + c[nn][1];
            rs1 += c[nn][2] + c[nn][3];
            uint32_t h0 = pack_bf16x2(c[nn][1], c[nn][0]);
            uint32_t h1 = pack_bf16x2(c[nn][3], c[nn][2]);
            shi[nn][0] = h0; shi[nn][1] = h1;
            float l00 = c[nn][0] - __uint_as_float(h0 << 16);
            float l01 = c[nn][1] - __uint_as_float(h0 & 0xFFFF0000u);
            float l10 = c[nn][2] - __uint_as_float(h1 << 16);
            float l11 = c[nn][3] - __uint_as_float(h1 & 0xFFFF0000u);
            slo[nn][0] = pack_bf16x2(l01, l00);
            slo[nn][1] = pack_bf16x2(l11, l10);
            size_t col = (size_t)m0 + nn * 8 + 2 * qc;
            *(float2*)&A[(size_t)(row0 + 16 * w + qr) * NTOK + col]     = make_float2(c[nn][0], c[nn][1]);
            *(float2*)&A[(size_t)(row0 + 16 * w + qr + 8) * NTOK + col] = make_float2(c[nn][2], c[nn][3]);
        }

        // ---- MMA2: out += SHi Zm(hi) + SHi Zm(lo) + SLo Zm(hi) ----
#pragma unroll
        for (int kk = 0; kk < 4; kk++) {
            uint32_t ah[4] = { shi[2 * kk][0], shi[2 * kk][1], shi[2 * kk + 1][0], shi[2 * kk + 1][1] };
            uint32_t al[4] = { slo[2 * kk][0], slo[2 * kk][1], slo[2 * kk + 1][0], slo[2 * kk + 1][1] };
#pragma unroll
            for (int nn = 0; nn < 16; nn++) {
                uint32_t bh[2], bl[2];
                uint32_t ba = zmB + (uint32_t)kk * (16u * RSTR) + (uint32_t)nn * 16u + b2off;
                ldsm_x2t(bh, ba);
                ldsm_x2t(bl, ba + ZM_LO_D);
                mma16816(o[nn], ah, bh);
                mma16816(o[nn], ah, bl);
                mma16816(o[nn], al, bh);
            }
        }
    }

    // ---- final: rowsum quad-reduce + store out partials ----
    rs0 += __shfl_xor_sync(0xffffffffu, rs0, 1);
    rs0 += __shfl_xor_sync(0xffffffffu, rs0, 2);
    rs1 += __shfl_xor_sync(0xffffffffu, rs1, 1);
    rs1 += __shfl_xor_sync(0xffffffffu, rs1, 2);
    if (qc == 0) {
        g_rs[(size_t)half * NTOK + row0 + 16 * w + qr]     = rs0;
        g_rs[(size_t)half * NTOK + row0 + 16 * w + qr + 8] = rs1;
    }
    float* dst = g_outpart + (size_t)half * NTOK * HID;
#pragma unroll
    for (int nn = 0; nn < 16; nn++) {
        size_t col = (size_t)nn * 8 + 2 * qc;
        *(float2*)&dst[(size_t)(row0 + 16 * w + qr) * HID + col]     = make_float2(o[nn][0], o[nn][1]);
        *(float2*)&dst[(size_t)(row0 + 16 * w + qr + 8) * HID + col] = make_float2(o[nn][2], o[nn][3]);
    }
}

// ===========================================================================
// K3a: inverse row sums
// ===========================================================================
__global__ __launch_bounds__(256) void k3_inv()
{
    int n = blockIdx.x * blockDim.x + threadIdx.x;
    g_inv[n] = 1.f / (g_rs[n] + g_rs[NTOK + n] + 1e-6f);
}

// K3b: out = (p0 + p1) * inv
__global__ __launch_bounds__(256) void k3_out(float* __restrict__ outp)
{
    int idx = blockIdx.x * blockDim.x + threadIdx.x;
    const float4* p0 = (const float4*)g_outpart;
    const float4* p1 = p0 + (NTOK * HID / 4);
    float4 a = p0[idx], b = p1[idx];
    float inv = g_inv[idx >> 5];
    float4 ov;
    ov.x = (a.x + b.x) * inv; ov.y = (a.y + b.y) * inv;
    ov.z = (a.z + b.z) * inv; ov.w = (a.w + b.w) * inv;
    ((float4*)outp)[idx] = ov;
}

// K3c: A *= inv[row]
__global__ __launch_bounds__(256) void k3_norm(float* __restrict__ A)
{
    long long i      = (long long)blockIdx.x * blockDim.x + threadIdx.x;
    long long stride = (long long)gridDim.x * blockDim.x;
    const long long total = (long long)NTOK * NTOK / 4;
    float4* A4 = (float4*)A;
    for (long long idx = i; idx < total; idx += stride) {
        int row  = (int)(idx >> 11);
        float sc = g_inv[row];
        float4 v = A4[idx];
        v.x *= sc; v.y *= sc; v.z *= sc; v.w *= sc;
        A4[idx] = v;
    }
}

extern "C" void kernel_launch(void* const* d_in, const int* in_sizes, int n_in,
                              void* d_out, int out_size)
{
    (void)in_sizes; (void)n_in; (void)out_size;
    const float* X = (const float*)d_in[0];
    const float* W = (const float*)d_in[1];
    float* outp = (float*)d_out;
    float* A    = (float*)d_out + (size_t)NTOK * HID;

    cudaFuncSetAttribute(k2_fused, cudaFuncAttributeMaxDynamicSharedMemorySize, SM_K2_BYTES);

    k1_gemm_z<<<NTOK / 32, 256>>>(X, W);
    k2_fused<<<128, 256, SM_K2_BYTES>>>(A);
    k3_inv<<<NTOK / 256, 256>>>();
    k3_out<<<(NTOK * HID / 4) / 256, 256>>>(outp);
    k3_norm<<<16384, 256>>>(A);
}

// round 14
// speedup vs baseline: 1.6410x; 1.2418x over previous
#include <cuda_runtime.h>
#include <cuda_fp16.h>
#include <cstdint>

#define NTOK 8192
#define INDIM 256
#define HID 128
#define BN 64
#define NT 64          // m-tiles per half (4096/64)

// ---------------- device scratch (no allocs allowed) ----------------
__device__ __half g_Zhi[NTOK * HID];
__device__ __half g_Zlo[NTOK * HID];
__device__ float g_outpart[2 * NTOK * HID];
__device__ float g_rs[2 * NTOK];
__device__ float g_inv[NTOK];

// ---------------- helpers ----------------
__device__ __forceinline__ uint32_t smem_u32(const void* p) {
    uint32_t a;
    asm("{ .reg .u64 t; cvta.to.shared.u64 t, %1; cvt.u32.u64 %0, t; }" : "=r"(a) : "l"(p));
    return a;
}
__device__ __forceinline__ void ldsm_x4(uint32_t a[4], uint32_t addr) {
    asm volatile("ldmatrix.sync.aligned.m8n8.x4.shared.b16 {%0,%1,%2,%3}, [%4];"
                 : "=r"(a[0]), "=r"(a[1]), "=r"(a[2]), "=r"(a[3]) : "r"(addr));
}
__device__ __forceinline__ void ldsm_x2(uint32_t b[2], uint32_t addr) {
    asm volatile("ldmatrix.sync.aligned.m8n8.x2.shared.b16 {%0,%1}, [%2];"
                 : "=r"(b[0]), "=r"(b[1]) : "r"(addr));
}
__device__ __forceinline__ void ldsm_x2t(uint32_t b[2], uint32_t addr) {
    asm volatile("ldmatrix.sync.aligned.m8n8.x2.trans.shared.b16 {%0,%1}, [%2];"
                 : "=r"(b[0]), "=r"(b[1]) : "r"(addr));
}
__device__ __forceinline__ void mma16816(float c[4], const uint32_t a[4], const uint32_t b[2]) {
    asm volatile("mma.sync.aligned.m16n8k16.row.col.f32.f16.f16.f32 "
                 "{%0,%1,%2,%3}, {%4,%5,%6,%7}, {%8,%9}, {%0,%1,%2,%3};"
                 : "+f"(c[0]), "+f"(c[1]), "+f"(c[2]), "+f"(c[3])
                 : "r"(a[0]), "r"(a[1]), "r"(a[2]), "r"(a[3]), "r"(b[0]), "r"(b[1]));
}
// pack two f32 -> f16x2: %1 -> upper half, %2 -> lower half (same convention as bf16x2)
__device__ __forceinline__ uint32_t pack_f16x2(float hi_upper, float lo_lower) {
    uint32_t r;
    asm("cvt.rn.f16x2.f32 %0, %1, %2;" : "=r"(r) : "f"(hi_upper), "f"(lo_lower));
    return r;
}

// ---------------- k2 smem layout (f16, row stride 136 elems = 272 B) ----------------
#define ZR_HI 0u          // [128][136]  34816 B
#define ZR_LO 34816u
#define ZM_HI 69632u      // [64][136]   17408 B  (lo never needed)
#define SM_K2_BYTES 87040u
#define RSTR 272u         // row stride bytes

// ===========================================================================
// K1: Z = X W^T (fp32 FFMA), emit fp16 hi/lo (row-major only)
// ===========================================================================
__global__ __launch_bounds__(256) void k1_gemm_z(const float* __restrict__ X,
                                                 const float* __restrict__ W)
{
    __shared__ float Wt[64][129];
    __shared__ float Xs[32][68];

    const int t    = threadIdx.x;
    const int row0 = blockIdx.x * 32;
    const int w    = t >> 5;
    const int lane = t & 31;

    float acc[4][4];
#pragma unroll
    for (int i = 0; i < 4; i++)
#pragma unroll
        for (int q = 0; q < 4; q++) acc[i][q] = 0.f;

    for (int c = 0; c < 4; c++) {
        const int i0 = c * 64;
#pragma unroll
        for (int rep = 0; rep < 8; rep++) {
            int f = rep * 256 + t;
            int h = f >> 4;
            int ii = (f & 15) << 2;
            float4 v = *(const float4*)&W[h * INDIM + i0 + ii];
            Wt[ii + 0][h] = v.x; Wt[ii + 1][h] = v.y;
            Wt[ii + 2][h] = v.z; Wt[ii + 3][h] = v.w;
        }
#pragma unroll
        for (int rep = 0; rep < 2; rep++) {
            int f = rep * 256 + t;
            int r = f >> 4;
            int ii = (f & 15) << 2;
            *(float4*)&Xs[r][ii] = *(const float4*)&X[(row0 + r) * INDIM + i0 + ii];
        }
        __syncthreads();
#pragma unroll 8
        for (int ii = 0; ii < 64; ii++) {
            float xv[4], wv[4];
#pragma unroll
            for (int i = 0; i < 4; i++) xv[i] = Xs[4 * w + i][ii];
#pragma unroll
            for (int q = 0; q < 4; q++) wv[q] = Wt[ii][lane + 32 * q];
#pragma unroll
            for (int i = 0; i < 4; i++)
#pragma unroll
                for (int q = 0; q < 4; q++)
                    acc[i][q] = fmaf(xv[i], wv[q], acc[i][q]);
        }
        __syncthreads();
    }

#pragma unroll
    for (int i = 0; i < 4; i++)
#pragma unroll
        for (int q = 0; q < 4; q++) {
            int n = row0 + 4 * w + i;
            int h = lane + 32 * q;
            float z = acc[i][q];
            __half hb = __float2half_rn(z);
            float hf = __half2float(hb);
            __half lb = __float2half_rn(z - hf);
            g_Zhi[n * HID + h] = hb;
            g_Zlo[n * HID + h] = lb;
        }
}

// ===========================================================================
// K2: fused mma.sync pipeline, fp16 2-term split (R9 structure).
//   MMA1: S = (Zrh + Zrl) Zmh^T   (2 mma per fragment pair)
//   MMA2: out += (Sh + Sl) Zmh    (2 mma, S reused from registers)
// 128 CTAs = 64 rowblocks x 2 halves, 256 threads.
// ===========================================================================
__global__ __launch_bounds__(256) void k2_fused(float* __restrict__ A)
{
    extern __shared__ __align__(16) char smem[];
    const uint32_t sb = smem_u32(smem);

    const int tid  = threadIdx.x;
    const int w    = tid >> 5;
    const int lane = tid & 31;
    const int qr   = lane >> 2;   // 0..7
    const int qc   = lane & 3;    // quad column
    const int rb   = blockIdx.x >> 1;
    const int half = blockIdx.x & 1;
    const int row0 = rb * 128;
    const int mbase = half * (NTOK / 2);

    // ---- load Zr hi/lo (one-time) ----
#pragma unroll
    for (int it = 0; it < 8; it++) {
        int f = it * 256 + tid;
        int r = f >> 4, ch = f & 15;
        uint32_t off = (uint32_t)r * RSTR + (uint32_t)ch * 16u;
        *(uint4*)(smem + ZR_HI + off) = *(const uint4*)&g_Zhi[(size_t)(row0 + r) * HID + ch * 8];
        *(uint4*)(smem + ZR_LO + off) = *(const uint4*)&g_Zlo[(size_t)(row0 + r) * HID + ch * 8];
    }

    // per-thread ldmatrix offsets (identical addressing to R9)
    const uint32_t aAddr  = sb + ZR_HI + (uint32_t)(16 * w + (lane & 15)) * RSTR
                            + (uint32_t)((lane >> 4) & 1) * 16u;              // A (Zr), x4 non-trans
    const uint32_t b1off  = (uint32_t)(lane & 7) * RSTR + (uint32_t)((lane >> 3) & 1) * 16u; // MMA1 B, x2
    const uint32_t b2off  = (uint32_t)((lane & 7) + 8 * ((lane >> 3) & 1)) * RSTR;           // MMA2 B, x2.trans

    float o[16][4];
#pragma unroll
    for (int nn = 0; nn < 16; nn++)
#pragma unroll
        for (int i = 0; i < 4; i++) o[nn][i] = 0.f;
    float rs0 = 0.f, rs1 = 0.f;

    for (int t = 0; t < NT; t++) {
        const int m0 = mbase + t * BN;
        __syncthreads();   // previous tile's ZM readers done (and Zr fill, iter 0)

        // ---- load Zm hi only [64,128] ----
#pragma unroll
        for (int it = 0; it < 4; it++) {
            int f = it * 256 + tid;
            int r = f >> 4, ch = f & 15;
            uint32_t off = (uint32_t)r * RSTR + (uint32_t)ch * 16u;
            *(uint4*)(smem + ZM_HI + off) = *(const uint4*)&g_Zhi[(size_t)(m0 + r) * HID + ch * 8];
        }
        __syncthreads();

        // ---- MMA1: S = Zrh Zmh^T + Zrl Zmh^T  ( = Z Zmh^T ) ----
        float c[8][4];
#pragma unroll
        for (int nn = 0; nn < 8; nn++)
#pragma unroll
            for (int i = 0; i < 4; i++) c[nn][i] = 0.f;

#pragma unroll
        for (int kk = 0; kk < 8; kk++) {
            uint32_t ah[4], al[4];
            ldsm_x4(ah, aAddr + kk * 32u);
            ldsm_x4(al, aAddr + (ZR_LO - ZR_HI) + kk * 32u);
#pragma unroll
            for (int nn = 0; nn < 8; nn++) {
                uint32_t bh[2];
                ldsm_x2(bh, sb + ZM_HI + (uint32_t)nn * (8u * RSTR) + kk * 32u + b1off);
                mma16816(c[nn], ah, bh);
                mma16816(c[nn], al, bh);
            }
        }

        // ---- epilogue in registers: relu, rowsum, A store, pack S hi/lo (fp16) ----
        uint32_t shi[8][2], slo[8][2];
#pragma unroll
        for (int nn = 0; nn < 8; nn++) {
#pragma unroll
            for (int i = 0; i < 4; i++) c[nn][i] = fmaxf(c[nn][i], 0.f);
            rs0 += c[nn][0] + c[nn][1];
            rs1 += c[nn][2] + c[nn][3];
            uint32_t h0 = pack_f16x2(c[nn][1], c[nn][0]);   // upper=c1, lower=c0
            uint32_t h1 = pack_f16x2(c[nn][3], c[nn][2]);
            shi[nn][0] = h0; shi[nn][1] = h1;
            __half2 h2a = *reinterpret_cast<const __half2*>(&h0);
            __half2 h2b = *reinterpret_cast<const __half2*>(&h1);
            float l00 = c[nn][0] - __half2float(__low2half(h2a));
            float l01 = c[nn][1] - __half2float(__high2half(h2a));
            float l10 = c[nn][2] - __half2float(__low2half(h2b));
            float l11 = c[nn][3] - __half2float(__high2half(h2b));
            slo[nn][0] = pack_f16x2(l01, l00);
            slo[nn][1] = pack_f16x2(l11, l10);
            // unnormalized A (rescaled by k3_norm)
            size_t col = (size_t)m0 + nn * 8 + 2 * qc;
            *(float2*)&A[(size_t)(row0 + 16 * w + qr) * NTOK + col]     = make_float2(c[nn][0], c[nn][1]);
            *(float2*)&A[(size_t)(row0 + 16 * w + qr + 8) * NTOK + col] = make_float2(c[nn][2], c[nn][3]);
        }

        // ---- MMA2: out += Sh Zmh + Sl Zmh  ( = S Zmh ) ----
#pragma unroll
        for (int kk = 0; kk < 4; kk++) {
            uint32_t ah[4] = { shi[2 * kk][0], shi[2 * kk][1], shi[2 * kk + 1][0], shi[2 * kk + 1][1] };
            uint32_t al[4] = { slo[2 * kk][0], slo[2 * kk][1], slo[2 * kk + 1][0], slo[2 * kk + 1][1] };
#pragma unroll
            for (int nn = 0; nn < 16; nn++) {
                uint32_t bh[2];
                ldsm_x2t(bh, sb + ZM_HI + (uint32_t)kk * (16u * RSTR) + (uint32_t)nn * 16u + b2off);
                mma16816(o[nn], ah, bh);
                mma16816(o[nn], al, bh);
            }
        }
    }

    // ---- final: rowsum quad-reduce + store out partials ----
    rs0 += __shfl_xor_sync(0xffffffffu, rs0, 1);
    rs0 += __shfl_xor_sync(0xffffffffu, rs0, 2);
    rs1 += __shfl_xor_sync(0xffffffffu, rs1, 1);
    rs1 += __shfl_xor_sync(0xffffffffu, rs1, 2);
    if (qc == 0) {
        g_rs[(size_t)half * NTOK + row0 + 16 * w + qr]     = rs0;
        g_rs[(size_t)half * NTOK + row0 + 16 * w + qr + 8] = rs1;
    }
    float* dst = g_outpart + (size_t)half * NTOK * HID;
#pragma unroll
    for (int nn = 0; nn < 16; nn++) {
        size_t col = (size_t)nn * 8 + 2 * qc;
        *(float2*)&dst[(size_t)(row0 + 16 * w + qr) * HID + col]     = make_float2(o[nn][0], o[nn][1]);
        *(float2*)&dst[(size_t)(row0 + 16 * w + qr + 8) * HID + col] = make_float2(o[nn][2], o[nn][3]);
    }
}

// ===========================================================================
// K3a: inverse row sums
// ===========================================================================
__global__ __launch_bounds__(256) void k3_inv()
{
    int n = blockIdx.x * blockDim.x + threadIdx.x;
    g_inv[n] = 1.f / (g_rs[n] + g_rs[NTOK + n] + 1e-6f);
}

// K3b: out = (p0 + p1) * inv
__global__ __launch_bounds__(256) void k3_out(float* __restrict__ outp)
{
    int idx = blockIdx.x * blockDim.x + threadIdx.x;
    const float4* p0 = (const float4*)g_outpart;
    const float4* p1 = p0 + (NTOK * HID / 4);
    float4 a = p0[idx], b = p1[idx];
    float inv = g_inv[idx >> 5];
    float4 ov;
    ov.x = (a.x + b.x) * inv; ov.y = (a.y + b.y) * inv;
    ov.z = (a.z + b.z) * inv; ov.w = (a.w + b.w) * inv;
    ((float4*)outp)[idx] = ov;
}

// K3c: A *= inv[row]
__global__ __launch_bounds__(256) void k3_norm(float* __restrict__ A)
{
    long long i      = (long long)blockIdx.x * blockDim.x + threadIdx.x;
    long long stride = (long long)gridDim.x * blockDim.x;
    const long long total = (long long)NTOK * NTOK / 4;
    float4* A4 = (float4*)A;
    for (long long idx = i; idx < total; idx += stride) {
        int row  = (int)(idx >> 11);
        float sc = g_inv[row];
        float4 v = A4[idx];
        v.x *= sc; v.y *= sc; v.z *= sc; v.w *= sc;
        A4[idx] = v;
    }
}

extern "C" void kernel_launch(void* const* d_in, const int* in_sizes, int n_in,
                              void* d_out, int out_size)
{
    (void)in_sizes; (void)n_in; (void)out_size;
    const float* X = (const float*)d_in[0];
    const float* W = (const float*)d_in[1];
    float* outp = (float*)d_out;
    float* A    = (float*)d_out + (size_t)NTOK * HID;

    cudaFuncSetAttribute(k2_fused, cudaFuncAttributeMaxDynamicSharedMemorySize, SM_K2_BYTES);

    k1_gemm_z<<<NTOK / 32, 256>>>(X, W);
    k2_fused<<<128, 256, SM_K2_BYTES>>>(A);
    k3_inv<<<NTOK / 256, 256>>>();
    k3_out<<<(NTOK * HID / 4) / 256, 256>>>(outp);
    k3_norm<<<16384, 256>>>(A);
}